// round 10
// baseline (speedup 1.0000x reference)
// v9 — fp32 rows (1 line/row), gathers at 4 nodes/warp × 8 lanes × float4:
// no cvt instructions, ~half the issue traffic/edge, same wavefronts/edge.
#include <cuda_runtime.h>
#include <cuda_fp16.h>

#define NN 100000
#define EE 1600000
#define GG 256
#define D_EMB 16
#define D_HID 32
#define CAP 64          // bucket capacity per node (deg ~ Poisson(16))

// ---------------- device scratch ----------------
__device__ float g_h[2 * NN * D_HID];     // fp32 rows, pre-scaled by dinv (128 B/row)
__device__ float g_h2[2 * NN * D_HID];
__device__ int   g_cur[2 * NN];           // scatter cursor == in-degree
__device__ int   g_csrc[2 * NN * CAP];    // bucketed src indices (local ids)
__device__ float g_pool[2 * GG * D_HID];
__device__ float g_cnt[2 * GG];

// ---------------- kernels ----------------

__global__ void k_zero_a() {
    int i = blockIdx.x * blockDim.x + threadIdx.x;
    if (i < 2 * NN) g_cur[i] = 0;
}
__global__ void k_zero_b() {
    int i = blockIdx.x * blockDim.x + threadIdx.x;
    if (i < 2 * GG * D_HID) g_pool[i] = 0.f;
    if (i < 2 * GG) g_cnt[i] = 0.f;
}

__global__ void k_scatter(const int* __restrict__ ei0, const int* __restrict__ ei1) {
    int e = blockIdx.x * blockDim.x + threadIdx.x;
    if (e >= 2 * EE) return;
    int side = e >= EE;
    const int* ei = side ? ei1 : ei0;
    int el = e - side * EE;
    int src = __ldg(&ei[el]);
    int dst = __ldg(&ei[EE + el]);
    int node = side * NN + dst;
    int p = atomicAdd(&g_cur[node], 1);
    if (p < CAP) g_csrc[node * CAP + p] = src;
}

// fused: x = emb[gid]+par*pW+pb ; h' = (x @ W1)*dinv -> fp32 rows
// 2 nodes/warp, 16 lanes/node, 2 output features per lane.
__global__ void __launch_bounds__(256) k_embed_mv16(
        const int* __restrict__ gid0, const float* __restrict__ par0,
        const int* __restrict__ gid1, const float* __restrict__ par1,
        const float* __restrict__ emb, const float* __restrict__ pW,
        const float* __restrict__ pb, const float* __restrict__ W1) {
    int gt = blockIdx.x * blockDim.x + threadIdx.x;
    int w = gt >> 5, lane = gt & 31;
    if (w >= NN) return;
    int sub = lane >> 4, f = lane & 15;
    int nid = 2 * w + sub;
    int side = nid >= NN;
    int n = nid - side * NN;
    const int*   gid = side ? gid1 : gid0;
    const float* par = side ? par1 : par0;
    int   g = __ldg(&gid[n]);
    float p = __ldg(&par[n]);
    float xv = __ldg(&emb[g * D_EMB + f]) + p * __ldg(&pW[f]) + __ldg(&pb[f]);
    int cnt = __ldg(&g_cur[nid]);
    float dn = rsqrtf((float)(cnt + 1));
    float zx = 0.f, zy = 0.f;
    int base = sub << 4;
#pragma unroll
    for (int k = 0; k < D_EMB; k++) {
        float a = __shfl_sync(0xffffffffu, xv, base + k);
        float2 wv = __ldg((const float2*)&W1[k * D_HID + 2 * f]);
        zx = fmaf(a, wv.x, zx);
        zy = fmaf(a, wv.y, zy);
    }
    ((float2*)g_h)[nid * 16 + f] = make_float2(zx * dn, zy * dn);
}

// gather core: 4 nodes/warp, 8 lanes/node, float4 per lane (features 4f..4f+3).
// All 8 lanes of a group broadcast-load the same idx words (no shfl needed).
__device__ __forceinline__ float4 gather_core4(const float4* __restrict__ H4,
                                               int nid, int f, int srow, int cnt) {
    float4 acc = __ldg(&H4[nid * 8 + f]);          // self row (pre-scaled)
    const int* idx = &g_csrc[nid * CAP];
    int i = 0;
    for (; i + 8 <= cnt; i += 8) {
        int4 a = __ldg((const int4*)(idx + i));
        int4 b = __ldg((const int4*)(idx + i + 4));
        float4 r0 = __ldg(&H4[(srow + a.x) * 8 + f]);
        float4 r1 = __ldg(&H4[(srow + a.y) * 8 + f]);
        float4 r2 = __ldg(&H4[(srow + a.z) * 8 + f]);
        float4 r3 = __ldg(&H4[(srow + a.w) * 8 + f]);
        float4 r4 = __ldg(&H4[(srow + b.x) * 8 + f]);
        float4 r5 = __ldg(&H4[(srow + b.y) * 8 + f]);
        float4 r6 = __ldg(&H4[(srow + b.z) * 8 + f]);
        float4 r7 = __ldg(&H4[(srow + b.w) * 8 + f]);
        acc.x += ((r0.x + r1.x) + (r2.x + r3.x)) + ((r4.x + r5.x) + (r6.x + r7.x));
        acc.y += ((r0.y + r1.y) + (r2.y + r3.y)) + ((r4.y + r5.y) + (r6.y + r7.y));
        acc.z += ((r0.z + r1.z) + (r2.z + r3.z)) + ((r4.z + r5.z) + (r6.z + r7.z));
        acc.w += ((r0.w + r1.w) + (r2.w + r3.w)) + ((r4.w + r5.w) + (r6.w + r7.w));
    }
    if (i + 4 <= cnt) {
        int4 a = __ldg((const int4*)(idx + i));
        float4 r0 = __ldg(&H4[(srow + a.x) * 8 + f]);
        float4 r1 = __ldg(&H4[(srow + a.y) * 8 + f]);
        float4 r2 = __ldg(&H4[(srow + a.z) * 8 + f]);
        float4 r3 = __ldg(&H4[(srow + a.w) * 8 + f]);
        acc.x += (r0.x + r1.x) + (r2.x + r3.x);
        acc.y += (r0.y + r1.y) + (r2.y + r3.y);
        acc.z += (r0.z + r1.z) + (r2.z + r3.z);
        acc.w += (r0.w + r1.w) + (r2.w + r3.w);
        i += 4;
    }
    for (; i < cnt; i++) {
        float4 r = __ldg(&H4[(srow + __ldg(&idx[i])) * 8 + f]);
        acc.x += r.x; acc.y += r.y; acc.z += r.z; acc.w += r.w;
    }
    return acc;
}

// fused: y = relu(dinv*(self+Σ)+b1);  h2' = (y @ W2)*dinv
__global__ void __launch_bounds__(256) k_agg_mv32(const float* __restrict__ b1,
                                                  const float* __restrict__ W2) {
    __shared__ float sW[D_HID * D_HID];
    for (int j = threadIdx.x; j < D_HID * D_HID; j += blockDim.x) sW[j] = W2[j];
    __syncthreads();
    int gt = blockIdx.x * blockDim.x + threadIdx.x;
    int w = gt >> 5, lane = gt & 31;
    if (w >= NN / 2) return;                  // (2*NN)/4 node-quads
    int grp = lane >> 3, f = lane & 7;
    int nid = 4 * w + grp;
    int side = nid >= NN;
    int srow = side * NN;
    int cnt_raw = __ldg(&g_cur[nid]);
    float dn = rsqrtf((float)(cnt_raw + 1));
    int cnt = min(cnt_raw, CAP);
    float4 acc = gather_core4((const float4*)g_h, nid, f, srow, cnt);
    float4 bb = __ldg((const float4*)(b1 + 4 * f));
    float yv[4];
    yv[0] = fmaxf(fmaf(acc.x, dn, bb.x), 0.f);
    yv[1] = fmaxf(fmaf(acc.y, dn, bb.y), 0.f);
    yv[2] = fmaxf(fmaf(acc.z, dn, bb.z), 0.f);
    yv[3] = fmaxf(fmaf(acc.w, dn, bb.w), 0.f);
    // matvec32: z[4f..4f+3] = Σ_k y[k] * W2[k][4f..4f+3]; y via group shfl
    float4 z = make_float4(0.f, 0.f, 0.f, 0.f);
    int base = grp << 3;
#pragma unroll
    for (int k = 0; k < D_HID; k++) {
        float a = __shfl_sync(0xffffffffu, yv[k & 3], base + (k >> 2));
        float4 wv = *(const float4*)&sW[k * D_HID + 4 * f];
        z.x = fmaf(a, wv.x, z.x);
        z.y = fmaf(a, wv.y, z.y);
        z.z = fmaf(a, wv.z, z.z);
        z.w = fmaf(a, wv.w, z.w);
    }
    z.x *= dn; z.y *= dn; z.z *= dn; z.w *= dn;
    ((float4*)g_h2)[nid * 8 + f] = z;
}

// fused: y = relu(dinv*(self+Σ)+b2);  pool += y
__global__ void __launch_bounds__(256) k_agg_pool(const float* __restrict__ b2,
                                                  const int* __restrict__ bat0,
                                                  const int* __restrict__ bat1) {
    int gt = blockIdx.x * blockDim.x + threadIdx.x;
    int w = gt >> 5, lane = gt & 31;
    if (w >= NN / 2) return;
    int grp = lane >> 3, f = lane & 7;
    int nid = 4 * w + grp;
    int side = nid >= NN;
    int n = nid - side * NN;
    int srow = side * NN;
    int cnt_raw = __ldg(&g_cur[nid]);
    float dn = rsqrtf((float)(cnt_raw + 1));
    int cnt = min(cnt_raw, CAP);
    float4 acc = gather_core4((const float4*)g_h2, nid, f, srow, cnt);
    float4 bb = __ldg((const float4*)(b2 + 4 * f));
    float y0 = fmaxf(fmaf(acc.x, dn, bb.x), 0.f);
    float y1 = fmaxf(fmaf(acc.y, dn, bb.y), 0.f);
    float y2 = fmaxf(fmaf(acc.z, dn, bb.z), 0.f);
    float y3 = fmaxf(fmaf(acc.w, dn, bb.w), 0.f);
    const int* bat = side ? bat1 : bat0;
    int gb = __ldg(&bat[n]);
    float* prow = &g_pool[(side * GG + gb) * D_HID + 4 * f];
    atomicAdd(prow + 0, y0);
    atomicAdd(prow + 1, y1);
    atomicAdd(prow + 2, y2);
    atomicAdd(prow + 3, y3);
    if (f == 0) atomicAdd(&g_cnt[side * GG + gb], 1.f);
}

// final MLP: [G,64] -> relu([G,32]) -> [G,1]   warp per graph
__global__ void __launch_bounds__(256) k_final(const float* __restrict__ fW1,
                                               const float* __restrict__ fb1,
                                               const float* __restrict__ fW2,
                                               const float* __restrict__ fb2,
                                               float* __restrict__ out) {
    int gt = blockIdx.x * blockDim.x + threadIdx.x;
    int g = gt >> 5, lane = gt & 31;
    if (g >= GG) return;
    float cl = 1.f / fmaxf(g_cnt[g], 1.f);
    float cr = 1.f / fmaxf(g_cnt[GG + g], 1.f);
    float pl = g_pool[g * D_HID + lane] * cl;
    float pr = g_pool[(GG + g) * D_HID + lane] * cr;
    float acc = __ldg(&fb1[lane]);
#pragma unroll
    for (int k = 0; k < D_HID; k++) {
        acc = fmaf(__shfl_sync(0xffffffffu, pl, k), __ldg(&fW1[k * D_HID + lane]), acc);
        acc = fmaf(__shfl_sync(0xffffffffu, pr, k), __ldg(&fW1[(D_HID + k) * D_HID + lane]), acc);
    }
    float v = fmaxf(acc, 0.f) * __ldg(&fW2[lane]);
#pragma unroll
    for (int o = 16; o > 0; o >>= 1) v += __shfl_down_sync(0xffffffffu, v, o);
    if (lane == 0) out[g] = v + __ldg(&fb2[0]);
}

// ---------------- launch ----------------

extern "C" void kernel_launch(void* const* d_in, const int* in_sizes, int n_in,
                              void* d_out, int out_size) {
    const int*   lhs_gid = (const int*)d_in[0];
    const float* lhs_par = (const float*)d_in[1];
    const int*   lhs_ei  = (const int*)d_in[2];
    const int*   lhs_b   = (const int*)d_in[3];
    const int*   rhs_gid = (const int*)d_in[4];
    const float* rhs_par = (const float*)d_in[5];
    const int*   rhs_ei  = (const int*)d_in[6];
    const int*   rhs_b   = (const int*)d_in[7];
    const float* emb = (const float*)d_in[8];
    const float* pW  = (const float*)d_in[9];
    const float* pb  = (const float*)d_in[10];
    const float* W1  = (const float*)d_in[11];
    const float* b1  = (const float*)d_in[12];
    const float* W2  = (const float*)d_in[13];
    const float* b2  = (const float*)d_in[14];
    const float* fW1 = (const float*)d_in[15];
    const float* fb1 = (const float*)d_in[16];
    const float* fW2 = (const float*)d_in[17];
    const float* fb2 = (const float*)d_in[18];
    float* out = (float*)d_out;

    const int TB = 256;
    const int EBLK = (NN * 32 + TB - 1) / TB;        // 2-node warps (embed)
    const int QBLK = ((NN / 2) * 32 + TB - 1) / TB;  // 4-node warps (gathers)

    k_zero_a<<<(2 * NN + TB - 1) / TB, TB>>>();                    // 1
    k_scatter<<<(2 * EE + TB - 1) / TB, TB>>>(lhs_ei, rhs_ei);     // 2
    k_embed_mv16<<<EBLK, TB>>>(lhs_gid, lhs_par, rhs_gid, rhs_par,
                               emb, pW, pb, W1);                   // 3
    k_agg_mv32<<<QBLK, TB>>>(b1, W2);                              // 4 <- ncu slot
    k_zero_b<<<(2 * GG * D_HID + TB - 1) / TB, TB>>>();            // 5
    k_agg_pool<<<QBLK, TB>>>(b2, lhs_b, rhs_b);                    // 6
    k_final<<<(GG * 32 + 255) / 256, 256>>>(fW1, fb1, fW2, fb2, out); // 7
}

// round 12
// speedup vs baseline: 1.0401x; 1.0401x over previous
// v10b — byte-identical resubmission of v10 after broker container flake.
// v8 base (fp16 rows, 2 nodes/warp, bucket CSR) + HADD2 pairwise-tree
// accumulation (cuts inner-loop issue ~40%) + int2 edge loads in scatter.
#include <cuda_runtime.h>
#include <cuda_fp16.h>

#define NN 100000
#define EE 1600000
#define GG 256
#define D_EMB 16
#define D_HID 32
#define CAP 64          // bucket capacity per node (deg ~ Poisson(16))

// ---------------- device scratch ----------------
__device__ __half g_h[2 * NN * D_HID];     // rows pre-scaled by dinv (half2 layout)
__device__ __half g_h2[2 * NN * D_HID];
__device__ int    g_cur[2 * NN];           // scatter cursor == in-degree
__device__ int    g_csrc[2 * NN * CAP];    // bucketed src indices (local ids)
__device__ float  g_pool[2 * GG * D_HID];
__device__ float  g_cnt[2 * GG];

// ---------------- kernels ----------------

__global__ void k_zero_a() {
    int i = blockIdx.x * blockDim.x + threadIdx.x;
    if (i < 2 * NN) g_cur[i] = 0;
}
__global__ void k_zero_b() {
    int i = blockIdx.x * blockDim.x + threadIdx.x;
    if (i < 2 * GG * D_HID) g_pool[i] = 0.f;
    if (i < 2 * GG) g_cnt[i] = 0.f;
}

// each thread handles 2 consecutive edges of one side (int2 loads)
__global__ void k_scatter(const int* __restrict__ ei0, const int* __restrict__ ei1) {
    int t = blockIdx.x * blockDim.x + threadIdx.x;
    if (t >= EE) return;                     // EE threads cover 2*EE edges
    int side = t >= (EE / 2);
    const int* ei = side ? ei1 : ei0;
    int el = (t - side * (EE / 2)) * 2;
    int2 src = __ldg((const int2*)(ei + el));
    int2 dst = __ldg((const int2*)(ei + EE + el));
    int node0 = side * NN + dst.x;
    int p0 = atomicAdd(&g_cur[node0], 1);
    if (p0 < CAP) g_csrc[node0 * CAP + p0] = src.x;
    int node1 = side * NN + dst.y;
    int p1 = atomicAdd(&g_cur[node1], 1);
    if (p1 < CAP) g_csrc[node1 * CAP + p1] = src.y;
}

// fused: x = emb[gid]+par*pW+pb ; h' = (x @ W1)*dinv -> fp16
// 2 nodes per warp, 16 lanes per node, 2 output features per lane.
__global__ void __launch_bounds__(256) k_embed_mv16(
        const int* __restrict__ gid0, const float* __restrict__ par0,
        const int* __restrict__ gid1, const float* __restrict__ par1,
        const float* __restrict__ emb, const float* __restrict__ pW,
        const float* __restrict__ pb, const float* __restrict__ W1) {
    int gt = blockIdx.x * blockDim.x + threadIdx.x;
    int w = gt >> 5, lane = gt & 31;
    if (w >= NN) return;
    int sub = lane >> 4, f = lane & 15;
    int nid = 2 * w + sub;
    int side = nid >= NN;
    int n = nid - side * NN;
    const int*   gid = side ? gid1 : gid0;
    const float* par = side ? par1 : par0;
    int   g = __ldg(&gid[n]);
    float p = __ldg(&par[n]);
    float xv = __ldg(&emb[g * D_EMB + f]) + p * __ldg(&pW[f]) + __ldg(&pb[f]);
    int cnt = __ldg(&g_cur[nid]);
    float dn = rsqrtf((float)(cnt + 1));
    float zx = 0.f, zy = 0.f;
    int base = sub << 4;
#pragma unroll
    for (int k = 0; k < D_EMB; k++) {
        float a = __shfl_sync(0xffffffffu, xv, base + k);
        float2 wv = __ldg((const float2*)&W1[k * D_HID + 2 * f]);
        zx = fmaf(a, wv.x, zx);
        zy = fmaf(a, wv.y, zy);
    }
    ((__half2*)g_h)[nid * 16 + f] = __floats2half2_rn(zx * dn, zy * dn);
}

// gather core: 16 lanes/node, half2/lane; HADD2 pairwise tree per 8 neighbors,
// converted to fp32 once per tree. Self row added in fp32.
__device__ __forceinline__ float2 gather_core(const __half2* __restrict__ H,
                                              int nid, int f, int srow, int cnt) {
    float2 acc = __half22float2(__ldg(&H[nid * 16 + f]));   // self (pre-scaled)
    const int* idx = &g_csrc[nid * CAP];
    int i = 0;
    for (; i + 8 <= cnt; i += 8) {
        int4 a = __ldg((const int4*)(idx + i));
        int4 b = __ldg((const int4*)(idx + i + 4));
        __half2 r0 = __ldg(&H[(srow + a.x) * 16 + f]);
        __half2 r1 = __ldg(&H[(srow + a.y) * 16 + f]);
        __half2 r2 = __ldg(&H[(srow + a.z) * 16 + f]);
        __half2 r3 = __ldg(&H[(srow + a.w) * 16 + f]);
        __half2 r4 = __ldg(&H[(srow + b.x) * 16 + f]);
        __half2 r5 = __ldg(&H[(srow + b.y) * 16 + f]);
        __half2 r6 = __ldg(&H[(srow + b.z) * 16 + f]);
        __half2 r7 = __ldg(&H[(srow + b.w) * 16 + f]);
        __half2 s01 = __hadd2(r0, r1), s23 = __hadd2(r2, r3);
        __half2 s45 = __hadd2(r4, r5), s67 = __hadd2(r6, r7);
        __half2 s = __hadd2(__hadd2(s01, s23), __hadd2(s45, s67));
        float2 fs = __half22float2(s);
        acc.x += fs.x;
        acc.y += fs.y;
    }
    if (i + 4 <= cnt) {
        int4 a = __ldg((const int4*)(idx + i));
        __half2 r0 = __ldg(&H[(srow + a.x) * 16 + f]);
        __half2 r1 = __ldg(&H[(srow + a.y) * 16 + f]);
        __half2 r2 = __ldg(&H[(srow + a.z) * 16 + f]);
        __half2 r3 = __ldg(&H[(srow + a.w) * 16 + f]);
        __half2 s = __hadd2(__hadd2(r0, r1), __hadd2(r2, r3));
        float2 fs = __half22float2(s);
        acc.x += fs.x;
        acc.y += fs.y;
        i += 4;
    }
    for (; i < cnt; i++) {
        float2 fv = __half22float2(__ldg(&H[(srow + __ldg(&idx[i])) * 16 + f]));
        acc.x += fv.x;
        acc.y += fv.y;
    }
    return acc;
}

// fused: y = relu(dinv*(self+Σ)+b1);  h2' = (y @ W2)*dinv
__global__ void __launch_bounds__(256) k_agg_mv32(const float* __restrict__ b1,
                                                  const float* __restrict__ W2) {
    __shared__ float sW[D_HID * D_HID];
    for (int j = threadIdx.x; j < D_HID * D_HID; j += blockDim.x) sW[j] = W2[j];
    __syncthreads();
    int gt = blockIdx.x * blockDim.x + threadIdx.x;
    int w = gt >> 5, lane = gt & 31;
    if (w >= NN) return;                      // NN node-pairs
    int sub = lane >> 4, f = lane & 15;
    int nid = 2 * w + sub;
    int side = nid >= NN;
    int srow = side * NN;
    int cnt_raw = __ldg(&g_cur[nid]);
    float dn = rsqrtf((float)(cnt_raw + 1));
    int cnt = min(cnt_raw, CAP);
    float2 acc = gather_core((const __half2*)g_h, nid, f, srow, cnt);
    float2 bb = __ldg((const float2*)(b1 + 2 * f));
    float yx = fmaxf(fmaf(acc.x, dn, bb.x), 0.f);
    float yy = fmaxf(fmaf(acc.y, dn, bb.y), 0.f);
    float zx = 0.f, zy = 0.f;
    int base = sub << 4;
#pragma unroll
    for (int k = 0; k < D_HID; k += 2) {
        int srcl = base + (k >> 1);
        float ax = __shfl_sync(0xffffffffu, yx, srcl);   // y[k]
        float ay = __shfl_sync(0xffffffffu, yy, srcl);   // y[k+1]
        float2 w0 = *(const float2*)&sW[k * D_HID + 2 * f];
        float2 w1 = *(const float2*)&sW[(k + 1) * D_HID + 2 * f];
        zx = fmaf(ax, w0.x, zx); zy = fmaf(ax, w0.y, zy);
        zx = fmaf(ay, w1.x, zx); zy = fmaf(ay, w1.y, zy);
    }
    ((__half2*)g_h2)[nid * 16 + f] = __floats2half2_rn(zx * dn, zy * dn);
}

// fused: y = relu(dinv*(self+Σ)+b2);  pool += y
__global__ void __launch_bounds__(256) k_agg_pool(const float* __restrict__ b2,
                                                  const int* __restrict__ bat0,
                                                  const int* __restrict__ bat1) {
    int gt = blockIdx.x * blockDim.x + threadIdx.x;
    int w = gt >> 5, lane = gt & 31;
    if (w >= NN) return;
    int sub = lane >> 4, f = lane & 15;
    int nid = 2 * w + sub;
    int side = nid >= NN;
    int n = nid - side * NN;
    int srow = side * NN;
    int cnt_raw = __ldg(&g_cur[nid]);
    float dn = rsqrtf((float)(cnt_raw + 1));
    int cnt = min(cnt_raw, CAP);
    float2 acc = gather_core((const __half2*)g_h2, nid, f, srow, cnt);
    float2 bb = __ldg((const float2*)(b2 + 2 * f));
    float yx = fmaxf(fmaf(acc.x, dn, bb.x), 0.f);
    float yy = fmaxf(fmaf(acc.y, dn, bb.y), 0.f);
    const int* bat = side ? bat1 : bat0;
    int g = __ldg(&bat[n]);
    float* prow = &g_pool[(side * GG + g) * D_HID + 2 * f];
    atomicAdd(prow, yx);
    atomicAdd(prow + 1, yy);
    if (f == 0) atomicAdd(&g_cnt[side * GG + g], 1.f);
}

// final MLP: [G,64] -> relu([G,32]) -> [G,1]   warp per graph
__global__ void __launch_bounds__(256) k_final(const float* __restrict__ fW1,
                                               const float* __restrict__ fb1,
                                               const float* __restrict__ fW2,
                                               const float* __restrict__ fb2,
                                               float* __restrict__ out) {
    int gt = blockIdx.x * blockDim.x + threadIdx.x;
    int g = gt >> 5, lane = gt & 31;
    if (g >= GG) return;
    float cl = 1.f / fmaxf(g_cnt[g], 1.f);
    float cr = 1.f / fmaxf(g_cnt[GG + g], 1.f);
    float pl = g_pool[g * D_HID + lane] * cl;
    float pr = g_pool[(GG + g) * D_HID + lane] * cr;
    float acc = __ldg(&fb1[lane]);
#pragma unroll
    for (int k = 0; k < D_HID; k++) {
        acc = fmaf(__shfl_sync(0xffffffffu, pl, k), __ldg(&fW1[k * D_HID + lane]), acc);
        acc = fmaf(__shfl_sync(0xffffffffu, pr, k), __ldg(&fW1[(D_HID + k) * D_HID + lane]), acc);
    }
    float v = fmaxf(acc, 0.f) * __ldg(&fW2[lane]);
#pragma unroll
    for (int o = 16; o > 0; o >>= 1) v += __shfl_down_sync(0xffffffffu, v, o);
    if (lane == 0) out[g] = v + __ldg(&fb2[0]);
}

// ---------------- launch ----------------

extern "C" void kernel_launch(void* const* d_in, const int* in_sizes, int n_in,
                              void* d_out, int out_size) {
    const int*   lhs_gid = (const int*)d_in[0];
    const float* lhs_par = (const float*)d_in[1];
    const int*   lhs_ei  = (const int*)d_in[2];
    const int*   lhs_b   = (const int*)d_in[3];
    const int*   rhs_gid = (const int*)d_in[4];
    const float* rhs_par = (const float*)d_in[5];
    const int*   rhs_ei  = (const int*)d_in[6];
    const int*   rhs_b   = (const int*)d_in[7];
    const float* emb = (const float*)d_in[8];
    const float* pW  = (const float*)d_in[9];
    const float* pb  = (const float*)d_in[10];
    const float* W1  = (const float*)d_in[11];
    const float* b1  = (const float*)d_in[12];
    const float* W2  = (const float*)d_in[13];
    const float* b2  = (const float*)d_in[14];
    const float* fW1 = (const float*)d_in[15];
    const float* fb1 = (const float*)d_in[16];
    const float* fW2 = (const float*)d_in[17];
    const float* fb2 = (const float*)d_in[18];
    float* out = (float*)d_out;

    const int TB = 256;
    const int PBLK = (NN * 32 + TB - 1) / TB;        // warp-per-node-pair kernels

    k_zero_a<<<(2 * NN + TB - 1) / TB, TB>>>();                    // 1
    k_scatter<<<(EE + TB - 1) / TB, TB>>>(lhs_ei, rhs_ei);         // 2
    k_embed_mv16<<<PBLK, TB>>>(lhs_gid, lhs_par, rhs_gid, rhs_par,
                               emb, pW, pb, W1);                   // 3
    k_agg_mv32<<<PBLK, TB>>>(b1, W2);                              // 4 <- ncu slot
    k_zero_b<<<(2 * GG * D_HID + TB - 1) / TB, TB>>>();            // 5
    k_agg_pool<<<PBLK, TB>>>(b2, lhs_b, rhs_b);                    // 6
    k_final<<<(GG * 32 + 255) / 256, 256>>>(fW1, fb1, fW2, fb2, out); // 7
}

// round 13
// speedup vs baseline: 1.0646x; 1.0236x over previous
// v11 — v10 base + epilogue off the smem crossbar: W2 via broadcast __ldg
// (1 wf/instr, halves agg_mv32's L1 cost) + red.v2.f32 pool atomics.
#include <cuda_runtime.h>
#include <cuda_fp16.h>

#define NN 100000
#define EE 1600000
#define GG 256
#define D_EMB 16
#define D_HID 32
#define CAP 64          // bucket capacity per node (deg ~ Poisson(16))

// ---------------- device scratch ----------------
__device__ __half g_h[2 * NN * D_HID];     // rows pre-scaled by dinv (half2 layout)
__device__ __half g_h2[2 * NN * D_HID];
__device__ int    g_cur[2 * NN];           // scatter cursor == in-degree
__device__ int    g_csrc[2 * NN * CAP];    // bucketed src indices (local ids)
__device__ float  g_pool[2 * GG * D_HID];
__device__ float  g_cnt[2 * GG];

// ---------------- kernels ----------------

__global__ void k_zero_a() {
    int i = blockIdx.x * blockDim.x + threadIdx.x;
    if (i < 2 * NN) g_cur[i] = 0;
}
__global__ void k_zero_b() {
    int i = blockIdx.x * blockDim.x + threadIdx.x;
    if (i < 2 * GG * D_HID) g_pool[i] = 0.f;
    if (i < 2 * GG) g_cnt[i] = 0.f;
}

// each thread handles 2 consecutive edges of one side (int2 loads)
__global__ void k_scatter(const int* __restrict__ ei0, const int* __restrict__ ei1) {
    int t = blockIdx.x * blockDim.x + threadIdx.x;
    if (t >= EE) return;                     // EE threads cover 2*EE edges
    int side = t >= (EE / 2);
    const int* ei = side ? ei1 : ei0;
    int el = (t - side * (EE / 2)) * 2;
    int2 src = __ldg((const int2*)(ei + el));
    int2 dst = __ldg((const int2*)(ei + EE + el));
    int node0 = side * NN + dst.x;
    int p0 = atomicAdd(&g_cur[node0], 1);
    if (p0 < CAP) g_csrc[node0 * CAP + p0] = src.x;
    int node1 = side * NN + dst.y;
    int p1 = atomicAdd(&g_cur[node1], 1);
    if (p1 < CAP) g_csrc[node1 * CAP + p1] = src.y;
}

// fused: x = emb[gid]+par*pW+pb ; h' = (x @ W1)*dinv -> fp16
// 2 nodes per warp, 16 lanes per node, 2 output features per lane.
__global__ void __launch_bounds__(256) k_embed_mv16(
        const int* __restrict__ gid0, const float* __restrict__ par0,
        const int* __restrict__ gid1, const float* __restrict__ par1,
        const float* __restrict__ emb, const float* __restrict__ pW,
        const float* __restrict__ pb, const float* __restrict__ W1) {
    int gt = blockIdx.x * blockDim.x + threadIdx.x;
    int w = gt >> 5, lane = gt & 31;
    if (w >= NN) return;
    int sub = lane >> 4, f = lane & 15;
    int nid = 2 * w + sub;
    int side = nid >= NN;
    int n = nid - side * NN;
    const int*   gid = side ? gid1 : gid0;
    const float* par = side ? par1 : par0;
    int   g = __ldg(&gid[n]);
    float p = __ldg(&par[n]);
    float xv = __ldg(&emb[g * D_EMB + f]) + p * __ldg(&pW[f]) + __ldg(&pb[f]);
    int cnt = __ldg(&g_cur[nid]);
    float dn = rsqrtf((float)(cnt + 1));
    float zx = 0.f, zy = 0.f;
    int base = sub << 4;
#pragma unroll
    for (int k = 0; k < D_EMB; k++) {
        float a = __shfl_sync(0xffffffffu, xv, base + k);
        float2 wv = __ldg((const float2*)&W1[k * D_HID + 2 * f]);
        zx = fmaf(a, wv.x, zx);
        zy = fmaf(a, wv.y, zy);
    }
    ((__half2*)g_h)[nid * 16 + f] = __floats2half2_rn(zx * dn, zy * dn);
}

// gather core: 16 lanes/node, half2/lane; HADD2 pairwise tree per 8 neighbors,
// converted to fp32 once per tree. Self row added in fp32.
__device__ __forceinline__ float2 gather_core(const __half2* __restrict__ H,
                                              int nid, int f, int srow, int cnt) {
    float2 acc = __half22float2(__ldg(&H[nid * 16 + f]));   // self (pre-scaled)
    const int* idx = &g_csrc[nid * CAP];
    int i = 0;
    for (; i + 8 <= cnt; i += 8) {
        int4 a = __ldg((const int4*)(idx + i));
        int4 b = __ldg((const int4*)(idx + i + 4));
        __half2 r0 = __ldg(&H[(srow + a.x) * 16 + f]);
        __half2 r1 = __ldg(&H[(srow + a.y) * 16 + f]);
        __half2 r2 = __ldg(&H[(srow + a.z) * 16 + f]);
        __half2 r3 = __ldg(&H[(srow + a.w) * 16 + f]);
        __half2 r4 = __ldg(&H[(srow + b.x) * 16 + f]);
        __half2 r5 = __ldg(&H[(srow + b.y) * 16 + f]);
        __half2 r6 = __ldg(&H[(srow + b.z) * 16 + f]);
        __half2 r7 = __ldg(&H[(srow + b.w) * 16 + f]);
        __half2 s01 = __hadd2(r0, r1), s23 = __hadd2(r2, r3);
        __half2 s45 = __hadd2(r4, r5), s67 = __hadd2(r6, r7);
        __half2 s = __hadd2(__hadd2(s01, s23), __hadd2(s45, s67));
        float2 fs = __half22float2(s);
        acc.x += fs.x;
        acc.y += fs.y;
    }
    if (i + 4 <= cnt) {
        int4 a = __ldg((const int4*)(idx + i));
        __half2 r0 = __ldg(&H[(srow + a.x) * 16 + f]);
        __half2 r1 = __ldg(&H[(srow + a.y) * 16 + f]);
        __half2 r2 = __ldg(&H[(srow + a.z) * 16 + f]);
        __half2 r3 = __ldg(&H[(srow + a.w) * 16 + f]);
        __half2 s = __hadd2(__hadd2(r0, r1), __hadd2(r2, r3));
        float2 fs = __half22float2(s);
        acc.x += fs.x;
        acc.y += fs.y;
        i += 4;
    }
    for (; i < cnt; i++) {
        float2 fv = __half22float2(__ldg(&H[(srow + __ldg(&idx[i])) * 16 + f]));
        acc.x += fv.x;
        acc.y += fv.y;
    }
    return acc;
}

// fused: y = relu(dinv*(self+Σ)+b1);  h2' = (y @ W2)*dinv
// W2 read via broadcast __ldg (both half-warps hit the same 128 B line -> 1 wf).
__global__ void __launch_bounds__(256) k_agg_mv32(const float* __restrict__ b1,
                                                  const float* __restrict__ W2) {
    int gt = blockIdx.x * blockDim.x + threadIdx.x;
    int w = gt >> 5, lane = gt & 31;
    if (w >= NN) return;                      // NN node-pairs
    int sub = lane >> 4, f = lane & 15;
    int nid = 2 * w + sub;
    int side = nid >= NN;
    int srow = side * NN;
    int cnt_raw = __ldg(&g_cur[nid]);
    float dn = rsqrtf((float)(cnt_raw + 1));
    int cnt = min(cnt_raw, CAP);
    float2 acc = gather_core((const __half2*)g_h, nid, f, srow, cnt);
    float2 bb = __ldg((const float2*)(b1 + 2 * f));
    float yx = fmaxf(fmaf(acc.x, dn, bb.x), 0.f);
    float yy = fmaxf(fmaf(acc.y, dn, bb.y), 0.f);
    float zx = 0.f, zy = 0.f;
    int base = sub << 4;
#pragma unroll
    for (int k = 0; k < D_HID; k += 2) {
        int srcl = base + (k >> 1);
        float ax = __shfl_sync(0xffffffffu, yx, srcl);   // y[k]
        float ay = __shfl_sync(0xffffffffu, yy, srcl);   // y[k+1]
        float2 w0 = __ldg((const float2*)&W2[k * D_HID + 2 * f]);
        float2 w1 = __ldg((const float2*)&W2[(k + 1) * D_HID + 2 * f]);
        zx = fmaf(ax, w0.x, zx); zy = fmaf(ax, w0.y, zy);
        zx = fmaf(ay, w1.x, zx); zy = fmaf(ay, w1.y, zy);
    }
    ((__half2*)g_h2)[nid * 16 + f] = __floats2half2_rn(zx * dn, zy * dn);
}

// fused: y = relu(dinv*(self+Σ)+b2);  pool += y (vector red)
__global__ void __launch_bounds__(256) k_agg_pool(const float* __restrict__ b2,
                                                  const int* __restrict__ bat0,
                                                  const int* __restrict__ bat1) {
    int gt = blockIdx.x * blockDim.x + threadIdx.x;
    int w = gt >> 5, lane = gt & 31;
    if (w >= NN) return;
    int sub = lane >> 4, f = lane & 15;
    int nid = 2 * w + sub;
    int side = nid >= NN;
    int n = nid - side * NN;
    int srow = side * NN;
    int cnt_raw = __ldg(&g_cur[nid]);
    float dn = rsqrtf((float)(cnt_raw + 1));
    int cnt = min(cnt_raw, CAP);
    float2 acc = gather_core((const __half2*)g_h2, nid, f, srow, cnt);
    float2 bb = __ldg((const float2*)(b2 + 2 * f));
    float yx = fmaxf(fmaf(acc.x, dn, bb.x), 0.f);
    float yy = fmaxf(fmaf(acc.y, dn, bb.y), 0.f);
    const int* bat = side ? bat1 : bat0;
    int g = __ldg(&bat[n]);
    float* prow = &g_pool[(side * GG + g) * D_HID + 2 * f];
    asm volatile("red.global.add.v2.f32 [%0], {%1, %2};"
                 :: "l"(prow), "f"(yx), "f"(yy) : "memory");
    if (f == 0) atomicAdd(&g_cnt[side * GG + g], 1.f);
}

// final MLP: [G,64] -> relu([G,32]) -> [G,1]   warp per graph
__global__ void __launch_bounds__(256) k_final(const float* __restrict__ fW1,
                                               const float* __restrict__ fb1,
                                               const float* __restrict__ fW2,
                                               const float* __restrict__ fb2,
                                               float* __restrict__ out) {
    int gt = blockIdx.x * blockDim.x + threadIdx.x;
    int g = gt >> 5, lane = gt & 31;
    if (g >= GG) return;
    float cl = 1.f / fmaxf(g_cnt[g], 1.f);
    float cr = 1.f / fmaxf(g_cnt[GG + g], 1.f);
    float pl = g_pool[g * D_HID + lane] * cl;
    float pr = g_pool[(GG + g) * D_HID + lane] * cr;
    float acc = __ldg(&fb1[lane]);
#pragma unroll
    for (int k = 0; k < D_HID; k++) {
        acc = fmaf(__shfl_sync(0xffffffffu, pl, k), __ldg(&fW1[k * D_HID + lane]), acc);
        acc = fmaf(__shfl_sync(0xffffffffu, pr, k), __ldg(&fW1[(D_HID + k) * D_HID + lane]), acc);
    }
    float v = fmaxf(acc, 0.f) * __ldg(&fW2[lane]);
#pragma unroll
    for (int o = 16; o > 0; o >>= 1) v += __shfl_down_sync(0xffffffffu, v, o);
    if (lane == 0) out[g] = v + __ldg(&fb2[0]);
}

// ---------------- launch ----------------

extern "C" void kernel_launch(void* const* d_in, const int* in_sizes, int n_in,
                              void* d_out, int out_size) {
    const int*   lhs_gid = (const int*)d_in[0];
    const float* lhs_par = (const float*)d_in[1];
    const int*   lhs_ei  = (const int*)d_in[2];
    const int*   lhs_b   = (const int*)d_in[3];
    const int*   rhs_gid = (const int*)d_in[4];
    const float* rhs_par = (const float*)d_in[5];
    const int*   rhs_ei  = (const int*)d_in[6];
    const int*   rhs_b   = (const int*)d_in[7];
    const float* emb = (const float*)d_in[8];
    const float* pW  = (const float*)d_in[9];
    const float* pb  = (const float*)d_in[10];
    const float* W1  = (const float*)d_in[11];
    const float* b1  = (const float*)d_in[12];
    const float* W2  = (const float*)d_in[13];
    const float* b2  = (const float*)d_in[14];
    const float* fW1 = (const float*)d_in[15];
    const float* fb1 = (const float*)d_in[16];
    const float* fW2 = (const float*)d_in[17];
    const float* fb2 = (const float*)d_in[18];
    float* out = (float*)d_out;

    const int TB = 256;
    const int PBLK = (NN * 32 + TB - 1) / TB;        // warp-per-node-pair kernels

    k_zero_a<<<(2 * NN + TB - 1) / TB, TB>>>();                    // 1
    k_scatter<<<(EE + TB - 1) / TB, TB>>>(lhs_ei, rhs_ei);         // 2
    k_embed_mv16<<<PBLK, TB>>>(lhs_gid, lhs_par, rhs_gid, rhs_par,
                               emb, pW, pb, W1);                   // 3
    k_agg_mv32<<<PBLK, TB>>>(b1, W2);                              // 4 <- ncu slot
    k_zero_b<<<(2 * GG * D_HID + TB - 1) / TB, TB>>>();            // 5
    k_agg_pool<<<PBLK, TB>>>(b2, lhs_b, rhs_b);                    // 6
    k_final<<<(GG * 32 + 255) / 256, 256>>>(fW1, fb1, fW2, fb2, out); // 7
}

// round 15
// speedup vs baseline: 1.0915x; 1.0253x over previous
// v12b — fix: W1 pack moved to block 1 (v12 tried threads 256..383 of a
// 256-thread block, leaving g_W1p zero → rel_err 1.0). Otherwise identical.
#include <cuda_runtime.h>
#include <cuda_fp16.h>

#define NN 100000
#define EE 1600000
#define GG 256
#define D_EMB 16
#define D_HID 32
#define CAP 64          // bucket capacity per node (deg ~ Poisson(16))

// ---------------- device scratch ----------------
__device__ __half g_h[2 * NN * D_HID];     // rows pre-scaled by dinv (half2 layout)
__device__ __half g_h2[2 * NN * D_HID];
__device__ int    g_cur[2 * NN];           // scatter cursor == in-degree
__device__ int    g_csrc[2 * NN * CAP];    // bucketed src indices (local ids)
__device__ float  g_pool[2 * GG * D_HID];
__device__ float  g_cnt[2 * GG];
// packed fp16 weights: entry (kp,f) = {W[2kp][2f], W[2kp][2f+1], W[2kp+1][2f], W[2kp+1][2f+1]}
__device__ uint2  g_W2p[16 * 16];          // k-pairs 0..15, f 0..15
__device__ uint2  g_W1p[8 * 16];           // k-pairs 0..7,  f 0..15

// ---------------- kernels ----------------

// zero cursors + pack W2 (block 0) and W1 (block 1) to fp16
__global__ void k_zero_a(const float* __restrict__ W1, const float* __restrict__ W2) {
    int i = blockIdx.x * blockDim.x + threadIdx.x;
    if (i < 2 * NN) g_cur[i] = 0;
    int t = threadIdx.x;
    if (blockIdx.x == 0) {                   // W2: 16 k-pairs x 16 f = 256 entries
        int kp = t >> 4, f = t & 15;
        __half* p = (__half*)g_W2p;
        p[t * 4 + 0] = __float2half(W2[(2 * kp) * D_HID + 2 * f]);
        p[t * 4 + 1] = __float2half(W2[(2 * kp) * D_HID + 2 * f + 1]);
        p[t * 4 + 2] = __float2half(W2[(2 * kp + 1) * D_HID + 2 * f]);
        p[t * 4 + 3] = __float2half(W2[(2 * kp + 1) * D_HID + 2 * f + 1]);
    } else if (blockIdx.x == 1 && t < 128) { // W1: 8 k-pairs x 16 f = 128 entries
        int kp = t >> 4, f = t & 15;
        __half* p = (__half*)g_W1p;
        p[t * 4 + 0] = __float2half(W1[(2 * kp) * D_HID + 2 * f]);
        p[t * 4 + 1] = __float2half(W1[(2 * kp) * D_HID + 2 * f + 1]);
        p[t * 4 + 2] = __float2half(W1[(2 * kp + 1) * D_HID + 2 * f]);
        p[t * 4 + 3] = __float2half(W1[(2 * kp + 1) * D_HID + 2 * f + 1]);
    }
}
__global__ void k_zero_b() {
    int i = blockIdx.x * blockDim.x + threadIdx.x;
    if (i < 2 * GG * D_HID) g_pool[i] = 0.f;
    if (i < 2 * GG) g_cnt[i] = 0.f;
}

// each thread handles 2 consecutive edges of one side (int2 loads)
__global__ void k_scatter(const int* __restrict__ ei0, const int* __restrict__ ei1) {
    int t = blockIdx.x * blockDim.x + threadIdx.x;
    if (t >= EE) return;                     // EE threads cover 2*EE edges
    int side = t >= (EE / 2);
    const int* ei = side ? ei1 : ei0;
    int el = (t - side * (EE / 2)) * 2;
    int2 src = __ldg((const int2*)(ei + el));
    int2 dst = __ldg((const int2*)(ei + EE + el));
    int node0 = side * NN + dst.x;
    int p0 = atomicAdd(&g_cur[node0], 1);
    if (p0 < CAP) g_csrc[node0 * CAP + p0] = src.x;
    int node1 = side * NN + dst.y;
    int p1 = atomicAdd(&g_cur[node1], 1);
    if (p1 < CAP) g_csrc[node1 * CAP + p1] = src.y;
}

// fused: x = emb[gid]+par*pW+pb ; h' = (x @ W1)*dinv -> fp16
// 2 nodes/warp, 16 lanes/node; W1 via packed-fp16 uint2 loads (1 wf / 2 k).
__global__ void __launch_bounds__(256) k_embed_mv16(
        const int* __restrict__ gid0, const float* __restrict__ par0,
        const int* __restrict__ gid1, const float* __restrict__ par1,
        const float* __restrict__ emb, const float* __restrict__ pW,
        const float* __restrict__ pb) {
    int gt = blockIdx.x * blockDim.x + threadIdx.x;
    int w = gt >> 5, lane = gt & 31;
    if (w >= NN) return;
    int sub = lane >> 4, f = lane & 15;
    int nid = 2 * w + sub;
    int side = nid >= NN;
    int n = nid - side * NN;
    const int*   gid = side ? gid1 : gid0;
    const float* par = side ? par1 : par0;
    int   g = __ldg(&gid[n]);
    float p = __ldg(&par[n]);
    float xv = __ldg(&emb[g * D_EMB + f]) + p * __ldg(&pW[f]) + __ldg(&pb[f]);
    int cnt = __ldg(&g_cur[nid]);
    float dn = rsqrtf((float)(cnt + 1));
    float zx = 0.f, zy = 0.f;
    int base = sub << 4;
#pragma unroll
    for (int kp = 0; kp < 8; kp++) {
        float a0 = __shfl_sync(0xffffffffu, xv, base + 2 * kp);       // x[2kp]
        float a1 = __shfl_sync(0xffffffffu, xv, base + 2 * kp + 1);   // x[2kp+1]
        uint2 raw = __ldg(&g_W1p[kp * 16 + f]);
        float2 w0 = __half22float2(*reinterpret_cast<__half2*>(&raw.x));
        float2 w1 = __half22float2(*reinterpret_cast<__half2*>(&raw.y));
        zx = fmaf(a0, w0.x, zx); zy = fmaf(a0, w0.y, zy);
        zx = fmaf(a1, w1.x, zx); zy = fmaf(a1, w1.y, zy);
    }
    ((__half2*)g_h)[nid * 16 + f] = __floats2half2_rn(zx * dn, zy * dn);
}

// gather core: 16 lanes/node, half2/lane; HADD2 pairwise tree per 8 neighbors.
__device__ __forceinline__ float2 gather_core(const __half2* __restrict__ H,
                                              int nid, int f, int srow, int cnt) {
    float2 acc = __half22float2(__ldg(&H[nid * 16 + f]));   // self (pre-scaled)
    const int* idx = &g_csrc[nid * CAP];
    int i = 0;
    for (; i + 8 <= cnt; i += 8) {
        int4 a = __ldg((const int4*)(idx + i));
        int4 b = __ldg((const int4*)(idx + i + 4));
        __half2 r0 = __ldg(&H[(srow + a.x) * 16 + f]);
        __half2 r1 = __ldg(&H[(srow + a.y) * 16 + f]);
        __half2 r2 = __ldg(&H[(srow + a.z) * 16 + f]);
        __half2 r3 = __ldg(&H[(srow + a.w) * 16 + f]);
        __half2 r4 = __ldg(&H[(srow + b.x) * 16 + f]);
        __half2 r5 = __ldg(&H[(srow + b.y) * 16 + f]);
        __half2 r6 = __ldg(&H[(srow + b.z) * 16 + f]);
        __half2 r7 = __ldg(&H[(srow + b.w) * 16 + f]);
        __half2 s01 = __hadd2(r0, r1), s23 = __hadd2(r2, r3);
        __half2 s45 = __hadd2(r4, r5), s67 = __hadd2(r6, r7);
        __half2 s = __hadd2(__hadd2(s01, s23), __hadd2(s45, s67));
        float2 fs = __half22float2(s);
        acc.x += fs.x;
        acc.y += fs.y;
    }
    if (i + 4 <= cnt) {
        int4 a = __ldg((const int4*)(idx + i));
        __half2 r0 = __ldg(&H[(srow + a.x) * 16 + f]);
        __half2 r1 = __ldg(&H[(srow + a.y) * 16 + f]);
        __half2 r2 = __ldg(&H[(srow + a.z) * 16 + f]);
        __half2 r3 = __ldg(&H[(srow + a.w) * 16 + f]);
        __half2 s = __hadd2(__hadd2(r0, r1), __hadd2(r2, r3));
        float2 fs = __half22float2(s);
        acc.x += fs.x;
        acc.y += fs.y;
        i += 4;
    }
    for (; i < cnt; i++) {
        float2 fv = __half22float2(__ldg(&H[(srow + __ldg(&idx[i])) * 16 + f]));
        acc.x += fv.x;
        acc.y += fv.y;
    }
    return acc;
}

// fused: y = relu(dinv*(self+Σ)+b1);  h2' = (y @ W2)*dinv
// W2 via packed-fp16 uint2 loads: 16 wf/warp (was 32).
__global__ void __launch_bounds__(256) k_agg_mv32(const float* __restrict__ b1) {
    int gt = blockIdx.x * blockDim.x + threadIdx.x;
    int w = gt >> 5, lane = gt & 31;
    if (w >= NN) return;                      // NN node-pairs
    int sub = lane >> 4, f = lane & 15;
    int nid = 2 * w + sub;
    int side = nid >= NN;
    int srow = side * NN;
    int cnt_raw = __ldg(&g_cur[nid]);
    float dn = rsqrtf((float)(cnt_raw + 1));
    int cnt = min(cnt_raw, CAP);
    float2 acc = gather_core((const __half2*)g_h, nid, f, srow, cnt);
    float2 bb = __ldg((const float2*)(b1 + 2 * f));
    float yx = fmaxf(fmaf(acc.x, dn, bb.x), 0.f);
    float yy = fmaxf(fmaf(acc.y, dn, bb.y), 0.f);
    float zx = 0.f, zy = 0.f;
    int base = sub << 4;
#pragma unroll
    for (int kp = 0; kp < 16; kp++) {
        float ax = __shfl_sync(0xffffffffu, yx, base + kp);   // y[2kp]
        float ay = __shfl_sync(0xffffffffu, yy, base + kp);   // y[2kp+1]
        uint2 raw = __ldg(&g_W2p[kp * 16 + f]);
        float2 w0 = __half22float2(*reinterpret_cast<__half2*>(&raw.x));
        float2 w1 = __half22float2(*reinterpret_cast<__half2*>(&raw.y));
        zx = fmaf(ax, w0.x, zx); zy = fmaf(ax, w0.y, zy);
        zx = fmaf(ay, w1.x, zx); zy = fmaf(ay, w1.y, zy);
    }
    ((__half2*)g_h2)[nid * 16 + f] = __floats2half2_rn(zx * dn, zy * dn);
}

// fused: y = relu(dinv*(self+Σ)+b2);  pool += y (vector red)
__global__ void __launch_bounds__(256) k_agg_pool(const float* __restrict__ b2,
                                                  const int* __restrict__ bat0,
                                                  const int* __restrict__ bat1) {
    int gt = blockIdx.x * blockDim.x + threadIdx.x;
    int w = gt >> 5, lane = gt & 31;
    if (w >= NN) return;
    int sub = lane >> 4, f = lane & 15;
    int nid = 2 * w + sub;
    int side = nid >= NN;
    int n = nid - side * NN;
    int srow = side * NN;
    int cnt_raw = __ldg(&g_cur[nid]);
    float dn = rsqrtf((float)(cnt_raw + 1));
    int cnt = min(cnt_raw, CAP);
    float2 acc = gather_core((const __half2*)g_h2, nid, f, srow, cnt);
    float2 bb = __ldg((const float2*)(b2 + 2 * f));
    float yx = fmaxf(fmaf(acc.x, dn, bb.x), 0.f);
    float yy = fmaxf(fmaf(acc.y, dn, bb.y), 0.f);
    const int* bat = side ? bat1 : bat0;
    int g = __ldg(&bat[n]);
    float* prow = &g_pool[(side * GG + g) * D_HID + 2 * f];
    asm volatile("red.global.add.v2.f32 [%0], {%1, %2};"
                 :: "l"(prow), "f"(yx), "f"(yy) : "memory");
    if (f == 0) atomicAdd(&g_cnt[side * GG + g], 1.f);
}

// final MLP: [G,64] -> relu([G,32]) -> [G,1]   warp per graph
__global__ void __launch_bounds__(256) k_final(const float* __restrict__ fW1,
                                               const float* __restrict__ fb1,
                                               const float* __restrict__ fW2,
                                               const float* __restrict__ fb2,
                                               float* __restrict__ out) {
    int gt = blockIdx.x * blockDim.x + threadIdx.x;
    int g = gt >> 5, lane = gt & 31;
    if (g >= GG) return;
    float cl = 1.f / fmaxf(g_cnt[g], 1.f);
    float cr = 1.f / fmaxf(g_cnt[GG + g], 1.f);
    float pl = g_pool[g * D_HID + lane] * cl;
    float pr = g_pool[(GG + g) * D_HID + lane] * cr;
    float acc = __ldg(&fb1[lane]);
#pragma unroll
    for (int k = 0; k < D_HID; k++) {
        acc = fmaf(__shfl_sync(0xffffffffu, pl, k), __ldg(&fW1[k * D_HID + lane]), acc);
        acc = fmaf(__shfl_sync(0xffffffffu, pr, k), __ldg(&fW1[(D_HID + k) * D_HID + lane]), acc);
    }
    float v = fmaxf(acc, 0.f) * __ldg(&fW2[lane]);
#pragma unroll
    for (int o = 16; o > 0; o >>= 1) v += __shfl_down_sync(0xffffffffu, v, o);
    if (lane == 0) out[g] = v + __ldg(&fb2[0]);
}

// ---------------- launch ----------------

extern "C" void kernel_launch(void* const* d_in, const int* in_sizes, int n_in,
                              void* d_out, int out_size) {
    const int*   lhs_gid = (const int*)d_in[0];
    const float* lhs_par = (const float*)d_in[1];
    const int*   lhs_ei  = (const int*)d_in[2];
    const int*   lhs_b   = (const int*)d_in[3];
    const int*   rhs_gid = (const int*)d_in[4];
    const float* rhs_par = (const float*)d_in[5];
    const int*   rhs_ei  = (const int*)d_in[6];
    const int*   rhs_b   = (const int*)d_in[7];
    const float* emb = (const float*)d_in[8];
    const float* pW  = (const float*)d_in[9];
    const float* pb  = (const float*)d_in[10];
    const float* W1  = (const float*)d_in[11];
    const float* b1  = (const float*)d_in[12];
    const float* W2  = (const float*)d_in[13];
    const float* b2  = (const float*)d_in[14];
    const float* fW1 = (const float*)d_in[15];
    const float* fb1 = (const float*)d_in[16];
    const float* fW2 = (const float*)d_in[17];
    const float* fb2 = (const float*)d_in[18];
    float* out = (float*)d_out;

    const int TB = 256;
    const int PBLK = (NN * 32 + TB - 1) / TB;        // warp-per-node-pair kernels

    k_zero_a<<<(2 * NN + TB - 1) / TB, TB>>>(W1, W2);              // 1 (+weight pack)
    k_scatter<<<(EE + TB - 1) / TB, TB>>>(lhs_ei, rhs_ei);         // 2
    k_embed_mv16<<<PBLK, TB>>>(lhs_gid, lhs_par, rhs_gid, rhs_par,
                               emb, pW, pb);                       // 3
    k_agg_mv32<<<PBLK, TB>>>(b1);                                  // 4 <- ncu slot
    k_zero_b<<<(2 * GG * D_HID + TB - 1) / TB, TB>>>();            // 5
    k_agg_pool<<<PBLK, TB>>>(b2, lhs_b, rhs_b);                    // 6
    k_final<<<(GG * 32 + 255) / 256, 256>>>(fW1, fb1, fW2, fb2, out); // 7
}

// round 16
// speedup vs baseline: 1.1016x; 1.0092x over previous
// v13 — issue-side cuts: HFMA2 epilogue in agg_mv32 (7 vs 11 issues/kp),
// global node ids in CSR (drops per-edge srow add in both gathers).
#include <cuda_runtime.h>
#include <cuda_fp16.h>

#define NN 100000
#define EE 1600000
#define GG 256
#define D_EMB 16
#define D_HID 32
#define CAP 64          // bucket capacity per node (deg ~ Poisson(16))

// ---------------- device scratch ----------------
__device__ __half g_h[2 * NN * D_HID];     // rows pre-scaled by dinv (half2 layout)
__device__ __half g_h2[2 * NN * D_HID];
__device__ int    g_cur[2 * NN];           // scatter cursor == in-degree
__device__ int    g_csrc[2 * NN * CAP];    // bucketed GLOBAL src ids (side*NN+src)
__device__ float  g_pool[2 * GG * D_HID];
__device__ float  g_cnt[2 * GG];
// packed fp16 weights: entry (kp,f) = {W[2kp][2f], W[2kp][2f+1], W[2kp+1][2f], W[2kp+1][2f+1]}
__device__ uint2  g_W2p[16 * 16];          // k-pairs 0..15, f 0..15
__device__ uint2  g_W1p[8 * 16];           // k-pairs 0..7,  f 0..15

// ---------------- kernels ----------------

// zero cursors + pack W2 (block 0) and W1 (block 1) to fp16
__global__ void k_zero_a(const float* __restrict__ W1, const float* __restrict__ W2) {
    int i = blockIdx.x * blockDim.x + threadIdx.x;
    if (i < 2 * NN) g_cur[i] = 0;
    int t = threadIdx.x;
    if (blockIdx.x == 0) {                   // W2: 16 k-pairs x 16 f = 256 entries
        int kp = t >> 4, f = t & 15;
        __half* p = (__half*)g_W2p;
        p[t * 4 + 0] = __float2half(W2[(2 * kp) * D_HID + 2 * f]);
        p[t * 4 + 1] = __float2half(W2[(2 * kp) * D_HID + 2 * f + 1]);
        p[t * 4 + 2] = __float2half(W2[(2 * kp + 1) * D_HID + 2 * f]);
        p[t * 4 + 3] = __float2half(W2[(2 * kp + 1) * D_HID + 2 * f + 1]);
    } else if (blockIdx.x == 1 && t < 128) { // W1: 8 k-pairs x 16 f = 128 entries
        int kp = t >> 4, f = t & 15;
        __half* p = (__half*)g_W1p;
        p[t * 4 + 0] = __float2half(W1[(2 * kp) * D_HID + 2 * f]);
        p[t * 4 + 1] = __float2half(W1[(2 * kp) * D_HID + 2 * f + 1]);
        p[t * 4 + 2] = __float2half(W1[(2 * kp + 1) * D_HID + 2 * f]);
        p[t * 4 + 3] = __float2half(W1[(2 * kp + 1) * D_HID + 2 * f + 1]);
    }
}
__global__ void k_zero_b() {
    int i = blockIdx.x * blockDim.x + threadIdx.x;
    if (i < 2 * GG * D_HID) g_pool[i] = 0.f;
    if (i < 2 * GG) g_cnt[i] = 0.f;
}

// each thread handles 2 consecutive edges of one side; stores GLOBAL src ids
__global__ void k_scatter(const int* __restrict__ ei0, const int* __restrict__ ei1) {
    int t = blockIdx.x * blockDim.x + threadIdx.x;
    if (t >= EE) return;                     // EE threads cover 2*EE edges
    int side = t >= (EE / 2);
    const int* ei = side ? ei1 : ei0;
    int el = (t - side * (EE / 2)) * 2;
    int sbase = side * NN;
    int2 src = __ldg((const int2*)(ei + el));
    int2 dst = __ldg((const int2*)(ei + EE + el));
    int node0 = sbase + dst.x;
    int p0 = atomicAdd(&g_cur[node0], 1);
    if (p0 < CAP) g_csrc[node0 * CAP + p0] = sbase + src.x;
    int node1 = sbase + dst.y;
    int p1 = atomicAdd(&g_cur[node1], 1);
    if (p1 < CAP) g_csrc[node1 * CAP + p1] = sbase + src.y;
}

// fused: x = emb[gid]+par*pW+pb ; h' = (x @ W1)*dinv -> fp16 (fp32 FFMA epilogue)
__global__ void __launch_bounds__(256) k_embed_mv16(
        const int* __restrict__ gid0, const float* __restrict__ par0,
        const int* __restrict__ gid1, const float* __restrict__ par1,
        const float* __restrict__ emb, const float* __restrict__ pW,
        const float* __restrict__ pb) {
    int gt = blockIdx.x * blockDim.x + threadIdx.x;
    int w = gt >> 5, lane = gt & 31;
    if (w >= NN) return;
    int sub = lane >> 4, f = lane & 15;
    int nid = 2 * w + sub;
    int side = nid >= NN;
    int n = nid - side * NN;
    const int*   gid = side ? gid1 : gid0;
    const float* par = side ? par1 : par0;
    int   g = __ldg(&gid[n]);
    float p = __ldg(&par[n]);
    float xv = __ldg(&emb[g * D_EMB + f]) + p * __ldg(&pW[f]) + __ldg(&pb[f]);
    int cnt = __ldg(&g_cur[nid]);
    float dn = rsqrtf((float)(cnt + 1));
    float zx = 0.f, zy = 0.f;
    int base = sub << 4;
#pragma unroll
    for (int kp = 0; kp < 8; kp++) {
        float a0 = __shfl_sync(0xffffffffu, xv, base + 2 * kp);       // x[2kp]
        float a1 = __shfl_sync(0xffffffffu, xv, base + 2 * kp + 1);   // x[2kp+1]
        uint2 raw = __ldg(&g_W1p[kp * 16 + f]);
        float2 w0 = __half22float2(*reinterpret_cast<__half2*>(&raw.x));
        float2 w1 = __half22float2(*reinterpret_cast<__half2*>(&raw.y));
        zx = fmaf(a0, w0.x, zx); zy = fmaf(a0, w0.y, zy);
        zx = fmaf(a1, w1.x, zx); zy = fmaf(a1, w1.y, zy);
    }
    ((__half2*)g_h)[nid * 16 + f] = __floats2half2_rn(zx * dn, zy * dn);
}

// gather core: 16 lanes/node, half2/lane; HADD2 pairwise tree per 8 neighbors.
// Indices are global node ids (no srow add).
__device__ __forceinline__ float2 gather_core(const __half2* __restrict__ H,
                                              int nid, int f, int cnt) {
    float2 acc = __half22float2(__ldg(&H[nid * 16 + f]));   // self (pre-scaled)
    const int* idx = &g_csrc[nid * CAP];
    int i = 0;
    for (; i + 8 <= cnt; i += 8) {
        int4 a = __ldg((const int4*)(idx + i));
        int4 b = __ldg((const int4*)(idx + i + 4));
        __half2 r0 = __ldg(&H[a.x * 16 + f]);
        __half2 r1 = __ldg(&H[a.y * 16 + f]);
        __half2 r2 = __ldg(&H[a.z * 16 + f]);
        __half2 r3 = __ldg(&H[a.w * 16 + f]);
        __half2 r4 = __ldg(&H[b.x * 16 + f]);
        __half2 r5 = __ldg(&H[b.y * 16 + f]);
        __half2 r6 = __ldg(&H[b.z * 16 + f]);
        __half2 r7 = __ldg(&H[b.w * 16 + f]);
        __half2 s01 = __hadd2(r0, r1), s23 = __hadd2(r2, r3);
        __half2 s45 = __hadd2(r4, r5), s67 = __hadd2(r6, r7);
        __half2 s = __hadd2(__hadd2(s01, s23), __hadd2(s45, s67));
        float2 fs = __half22float2(s);
        acc.x += fs.x;
        acc.y += fs.y;
    }
    if (i + 4 <= cnt) {
        int4 a = __ldg((const int4*)(idx + i));
        __half2 r0 = __ldg(&H[a.x * 16 + f]);
        __half2 r1 = __ldg(&H[a.y * 16 + f]);
        __half2 r2 = __ldg(&H[a.z * 16 + f]);
        __half2 r3 = __ldg(&H[a.w * 16 + f]);
        __half2 s = __hadd2(__hadd2(r0, r1), __hadd2(r2, r3));
        float2 fs = __half22float2(s);
        acc.x += fs.x;
        acc.y += fs.y;
        i += 4;
    }
    for (; i < cnt; i++) {
        float2 fv = __half22float2(__ldg(&H[__ldg(&idx[i]) * 16 + f]));
        acc.x += fv.x;
        acc.y += fv.y;
    }
    return acc;
}

// fused: y = relu(dinv*(self+Σ)+b1);  h2' = (y @ W2)*dinv
// Epilogue: HFMA2 with half2 z accumulator — 7 issues per k-pair.
__global__ void __launch_bounds__(256) k_agg_mv32(const float* __restrict__ b1) {
    int gt = blockIdx.x * blockDim.x + threadIdx.x;
    int w = gt >> 5, lane = gt & 31;
    if (w >= NN) return;                      // NN node-pairs
    int sub = lane >> 4, f = lane & 15;
    int nid = 2 * w + sub;
    int cnt_raw = __ldg(&g_cur[nid]);
    float dn = rsqrtf((float)(cnt_raw + 1));
    int cnt = min(cnt_raw, CAP);
    float2 acc = gather_core((const __half2*)g_h, nid, f, cnt);
    float2 bb = __ldg((const float2*)(b1 + 2 * f));
    float yx = fmaxf(fmaf(acc.x, dn, bb.x), 0.f);
    float yy = fmaxf(fmaf(acc.y, dn, bb.y), 0.f);
    __half2 zp = __float2half2_rn(0.f);
    int base = sub << 4;
#pragma unroll
    for (int kp = 0; kp < 16; kp++) {
        float ax = __shfl_sync(0xffffffffu, yx, base + kp);   // y[2kp]
        float ay = __shfl_sync(0xffffffffu, yy, base + kp);   // y[2kp+1]
        __half2 ha = __float2half2_rn(ax);                    // (ax,ax)
        __half2 hb = __float2half2_rn(ay);                    // (ay,ay)
        uint2 raw = __ldg(&g_W2p[kp * 16 + f]);
        zp = __hfma2(ha, *reinterpret_cast<__half2*>(&raw.x), zp);
        zp = __hfma2(hb, *reinterpret_cast<__half2*>(&raw.y), zp);
    }
    float2 zf = __half22float2(zp);
    ((__half2*)g_h2)[nid * 16 + f] = __floats2half2_rn(zf.x * dn, zf.y * dn);
}

// fused: y = relu(dinv*(self+Σ)+b2);  pool += y (vector red)
__global__ void __launch_bounds__(256) k_agg_pool(const float* __restrict__ b2,
                                                  const int* __restrict__ bat0,
                                                  const int* __restrict__ bat1) {
    int gt = blockIdx.x * blockDim.x + threadIdx.x;
    int w = gt >> 5, lane = gt & 31;
    if (w >= NN) return;
    int sub = lane >> 4, f = lane & 15;
    int nid = 2 * w + sub;
    int side = nid >= NN;
    int n = nid - side * NN;
    int cnt_raw = __ldg(&g_cur[nid]);
    float dn = rsqrtf((float)(cnt_raw + 1));
    int cnt = min(cnt_raw, CAP);
    float2 acc = gather_core((const __half2*)g_h2, nid, f, cnt);
    float2 bb = __ldg((const float2*)(b2 + 2 * f));
    float yx = fmaxf(fmaf(acc.x, dn, bb.x), 0.f);
    float yy = fmaxf(fmaf(acc.y, dn, bb.y), 0.f);
    const int* bat = side ? bat1 : bat0;
    int g = __ldg(&bat[n]);
    float* prow = &g_pool[(side * GG + g) * D_HID + 2 * f];
    asm volatile("red.global.add.v2.f32 [%0], {%1, %2};"
                 :: "l"(prow), "f"(yx), "f"(yy) : "memory");
    if (f == 0) atomicAdd(&g_cnt[side * GG + g], 1.f);
}

// final MLP: [G,64] -> relu([G,32]) -> [G,1]   warp per graph
__global__ void __launch_bounds__(256) k_final(const float* __restrict__ fW1,
                                               const float* __restrict__ fb1,
                                               const float* __restrict__ fW2,
                                               const float* __restrict__ fb2,
                                               float* __restrict__ out) {
    int gt = blockIdx.x * blockDim.x + threadIdx.x;
    int g = gt >> 5, lane = gt & 31;
    if (g >= GG) return;
    float cl = 1.f / fmaxf(g_cnt[g], 1.f);
    float cr = 1.f / fmaxf(g_cnt[GG + g], 1.f);
    float pl = g_pool[g * D_HID + lane] * cl;
    float pr = g_pool[(GG + g) * D_HID + lane] * cr;
    float acc = __ldg(&fb1[lane]);
#pragma unroll
    for (int k = 0; k < D_HID; k++) {
        acc = fmaf(__shfl_sync(0xffffffffu, pl, k), __ldg(&fW1[k * D_HID + lane]), acc);
        acc = fmaf(__shfl_sync(0xffffffffu, pr, k), __ldg(&fW1[(D_HID + k) * D_HID + lane]), acc);
    }
    float v = fmaxf(acc, 0.f) * __ldg(&fW2[lane]);
#pragma unroll
    for (int o = 16; o > 0; o >>= 1) v += __shfl_down_sync(0xffffffffu, v, o);
    if (lane == 0) out[g] = v + __ldg(&fb2[0]);
}

// ---------------- launch ----------------

extern "C" void kernel_launch(void* const* d_in, const int* in_sizes, int n_in,
                              void* d_out, int out_size) {
    const int*   lhs_gid = (const int*)d_in[0];
    const float* lhs_par = (const float*)d_in[1];
    const int*   lhs_ei  = (const int*)d_in[2];
    const int*   lhs_b   = (const int*)d_in[3];
    const int*   rhs_gid = (const int*)d_in[4];
    const float* rhs_par = (const float*)d_in[5];
    const int*   rhs_ei  = (const int*)d_in[6];
    const int*   rhs_b   = (const int*)d_in[7];
    const float* emb = (const float*)d_in[8];
    const float* pW  = (const float*)d_in[9];
    const float* pb  = (const float*)d_in[10];
    const float* W1  = (const float*)d_in[11];
    const float* b1  = (const float*)d_in[12];
    const float* W2  = (const float*)d_in[13];
    const float* b2  = (const float*)d_in[14];
    const float* fW1 = (const float*)d_in[15];
    const float* fb1 = (const float*)d_in[16];
    const float* fW2 = (const float*)d_in[17];
    const float* fb2 = (const float*)d_in[18];
    float* out = (float*)d_out;

    const int TB = 256;
    const int PBLK = (NN * 32 + TB - 1) / TB;        // warp-per-node-pair kernels

    k_zero_a<<<(2 * NN + TB - 1) / TB, TB>>>(W1, W2);              // 1 (+weight pack)
    k_scatter<<<(EE + TB - 1) / TB, TB>>>(lhs_ei, rhs_ei);         // 2
    k_embed_mv16<<<PBLK, TB>>>(lhs_gid, lhs_par, rhs_gid, rhs_par,
                               emb, pW, pb);                       // 3
    k_agg_mv32<<<PBLK, TB>>>(b1);                                  // 4 <- ncu slot
    k_zero_b<<<(2 * GG * D_HID + TB - 1) / TB, TB>>>();            // 5
    k_agg_pool<<<PBLK, TB>>>(b2, lhs_b, rhs_b);                    // 6
    k_final<<<(GG * 32 + 255) / 256, 256>>>(fW1, fb1, fW2, fb2, out); // 7
}